// round 9
// baseline (speedup 1.0000x reference)
#include <cuda_runtime.h>

#define NN 40960
#define PT (4*NN)

__device__ float g_f[(long)PT*32];   // f = relu(s2*(W2@feat)+b2), [point][32]
__device__ float g_z[(long)PT*32];   // z = s3 * (W3a @ f), [point][32]
__device__ int g_is64;

__device__ __forceinline__ unsigned long long pack2(float lo, float hi){
    unsigned long long r;
    asm("mov.b64 %0, {%1, %2};" : "=l"(r) : "f"(lo), "f"(hi));
    return r;
}
__device__ __forceinline__ void unpack2(unsigned long long v, float& lo, float& hi){
    asm("mov.b64 {%0, %1}, %2;" : "=f"(lo), "=f"(hi) : "l"(v));
}
__device__ __forceinline__ unsigned long long fma2(unsigned long long a, unsigned long long b, unsigned long long c){
    unsigned long long d;
    asm("fma.rn.f32x2 %0, %1, %2, %3;" : "=l"(d) : "l"(a), "l"(b), "l"(c));
    return d;
}

// ---------------------------------------------------------------------------
// Kernel A: per point  f = relu(s2*(W2@x)+b2);  z = s3*(W3a@f)
__global__ void __launch_bounds__(256) kernelA(
    const float* __restrict__ feat,
    const float* __restrict__ W2, const float* __restrict__ g2, const float* __restrict__ b2,
    const float* __restrict__ W3, const float* __restrict__ g3,
    const int* __restrict__ neigh32)
{
    __shared__ __align__(16) float tile[64*68];      // [n][d] pitch 68 (16B rows)
    __shared__ __align__(16) float hs[8][2][32];     // double-buffered f

    const int tid  = threadIdx.x;
    const int lane = tid & 31;
    const int wid  = tid >> 5;

    if (blockIdx.x == 0 && tid == 0){
        int allzero = 1;
        #pragma unroll 1
        for (int i = 0; i < 128; i++)
            if (neigh32[2*i + 1] != 0) { allzero = 0; break; }
        g_is64 = allzero;
    }

    const float inv = rsqrtf(1.0f + 1e-5f);
    const float s2 = g2[lane]*inv, bb2 = b2[lane];
    const float s3 = g3[lane]*inv;

    unsigned long long w2p[32], w3ap[16];
    for (int i = tid; i < 2048; i += 256) tile[(i>>6)*66 + (i&63)] = W2[i];
    __syncthreads();
    #pragma unroll
    for (int c = 0; c < 32; c++)
        w2p[c] = pack2(tile[lane*66 + 2*c]*s2, tile[lane*66 + 2*c + 1]*s2);
    __syncthreads();
    for (int i = tid; i < 2048; i += 256) tile[(i>>6)*66 + (i&63)] = W3[i];
    __syncthreads();
    #pragma unroll
    for (int c = 0; c < 16; c++)
        w3ap[c] = pack2(tile[lane*66 + 2*c]*s3, tile[lane*66 + 2*c + 1]*s3);

    #pragma unroll 1
    for (int blk = blockIdx.x; blk < 2560; blk += gridDim.x){
        const int b  = blk / 640;
        const int n0 = (blk - b*640) * 64;
        const float* fb = feat + (long)b*64*NN;
        __syncthreads();
        for (int i = tid; i < 4096; i += 256){
            int d = i >> 6, n = i & 63;
            tile[n*68 + d] = fb[(long)d*NN + n0 + n];
        }
        __syncthreads();

        #pragma unroll 1
        for (int j = 0; j < 8; j++){
            const int n = wid*8 + j;
            const ulonglong2* xp2 = (const ulonglong2*)(tile + n*68);
            unsigned long long a0=0ull, a1=0ull, a2=0ull, a3=0ull;
            #pragma unroll
            for (int c = 0; c < 16; c += 2){
                ulonglong2 v0 = xp2[c], v1 = xp2[c+1];
                a0 = fma2(w2p[2*c+0], v0.x, a0);
                a1 = fma2(w2p[2*c+1], v0.y, a1);
                a2 = fma2(w2p[2*c+2], v1.x, a2);
                a3 = fma2(w2p[2*c+3], v1.y, a3);
            }
            float l0,h0,l1,h1,l2,h2,l3,h3;
            unpack2(a0,l0,h0); unpack2(a1,l1,h1); unpack2(a2,l2,h2); unpack2(a3,l3,h3);
            float f = fmaxf((l0+h0)+(l1+h1)+(l2+h2)+(l3+h3) + bb2, 0.0f);

            const long p = (long)b*NN + n0 + n;
            float* hb = hs[wid][j & 1];
            hb[lane] = f;
            g_f[p*32 + lane] = f;
            __syncwarp();

            const ulonglong2* hp2 = (const ulonglong2*)hb;
            unsigned long long z0=0ull, z1=0ull, z2=0ull, z3=0ull;
            #pragma unroll
            for (int c = 0; c < 8; c += 2){
                ulonglong2 v0 = hp2[c], v1 = hp2[c+1];
                z0 = fma2(w3ap[2*c+0], v0.x, z0);
                z1 = fma2(w3ap[2*c+1], v0.y, z1);
                z2 = fma2(w3ap[2*c+2], v1.x, z2);
                z3 = fma2(w3ap[2*c+3], v1.y, z3);
            }
            unpack2(z0,l0,h0); unpack2(z1,l1,h1); unpack2(z2,l2,h2); unpack2(z3,l3,h3);
            g_z[p*32 + lane] = (l0+h0)+(l1+h1)+(l2+h2)+(l3+h3);
        }
    }
}

// ---------------------------------------------------------------------------
// Kernel B: persistent, one warp per point; block-cooperative W4 epilogue.
__global__ void __launch_bounds__(256, 2) kernelB(
    const float* __restrict__ xyz, const int* __restrict__ neigh32,
    const float* __restrict__ W1, const float* __restrict__ g1, const float* __restrict__ b1,
    const float* __restrict__ W3, const float* __restrict__ g3, const float* __restrict__ b3,
    const float* __restrict__ W4, const float* __restrict__ g4, const float* __restrict__ b4,
    float* __restrict__ out)
{
    __shared__ __align__(16) float sW4T[64*65];      // [c][o] pitch 65, scale folded
    __shared__ float sB4[64];
    __shared__ __align__(16) float sR[8][16*4];      // per-warp (dist,rx,ry,rz)x16
    __shared__ __align__(16) float sH1[8][16*32];    // per-warp h1[k][h]
    __shared__ __align__(16) float sX[64*10];        // [c][j] pitch 10 (epilogue operand)

    const int tid  = threadIdx.x;
    const int lane = tid & 31;
    const int wid  = tid >> 5;
    const float inv = rsqrtf(1.0f + 1e-5f);

    // W1 folded: u=[dist,r,P,Q], Q=P-r => W1@u = wd*dist + (Wr-WQ)@r + (WP+WQ)@P
    const float s1 = g1[lane]*inv, bb1 = b1[lane];
    const float s3 = g3[lane]*inv, bb3 = b3[lane];
    float wd   = W1[lane*10 + 0]*s1;
    float wrx  = (W1[lane*10 + 1] - W1[lane*10 + 7])*s1;
    float wry  = (W1[lane*10 + 2] - W1[lane*10 + 8])*s1;
    float wrz  = (W1[lane*10 + 3] - W1[lane*10 + 9])*s1;
    float wpx  = (W1[lane*10 + 4] + W1[lane*10 + 7])*s1;
    float wpy  = (W1[lane*10 + 5] + W1[lane*10 + 8])*s1;
    float wpz  = (W1[lane*10 + 6] + W1[lane*10 + 9])*s1;
    const unsigned long long w1a = pack2(wd,  wrx);   // * (dist, rx)
    const unsigned long long w1b = pack2(wry, wrz);   // * (ry, rz)

    // stage W3 coalesced into sH1, read rows (pitch 66)
    unsigned long long w3bp[16];
    {
        float* wt = (float*)sH1;
        for (int i = tid; i < 2048; i += 256) wt[(i>>6)*66 + (i&63)] = W3[i];
        __syncthreads();
        #pragma unroll
        for (int c = 0; c < 16; c++)
            w3bp[c] = pack2(wt[lane*66 + 32 + 2*c]*s3, wt[lane*66 + 33 + 2*c]*s3);
        __syncthreads();
    }
    // W4 transposed + scale folded: sW4T[c*65 + o] = W4[o][c]*s4[o]
    for (int i = tid; i < 4096; i += 256){
        int o = i >> 6, c = i & 63;
        sW4T[c*65 + o] = W4[o*64 + c] * (g4[o]*inv);
    }
    if (tid < 64) sB4[tid] = b4[tid];

    const int is64 = g_is64;
    __syncthreads();

    const int olocal = lane >> 2;          // epilogue: output o = wid*8 + olocal
    const int jp     = lane & 3;           // epilogue: points j = 2jp, 2jp+1

    #pragma unroll 1
    for (int grp = blockIdx.x; grp < PT/8; grp += gridDim.x){
        const int p = grp*8 + wid;
        const int b = p / NN, n = p - b*NN;
        const float* xb = xyz + (long)b*NN*3;
        const float* zb = g_z + (long)b*NN*32;
        const float Px = xb[n*3+0], Py = xb[n*3+1], Pz = xb[n*3+2];

        // phase 0: lanes<16 compute their neighbor's geometry in parallel
        int myidx = 0;
        if (lane < 16){
            myidx = is64 ? neigh32[2*(p*16 + lane)] : neigh32[p*16 + lane];
            float Qx = xb[myidx*3+0], Qy = xb[myidx*3+1], Qz = xb[myidx*3+2];
            float rx = Px - Qx, ry = Py - Qy, rz = Pz - Qz;
            float dist = sqrtf(rx*rx + ry*ry + rz*rz);
            ((float4*)sR[wid])[lane] = make_float4(dist, rx, ry, rz);
        }

        // batched z gathers (MLP=16)
        float zk[16];
        #pragma unroll
        for (int k = 0; k < 16; k++){
            int id = __shfl_sync(0xffffffffu, myidx, k);
            zk[k] = zb[id*32 + lane];
        }
        __syncwarp();

        const unsigned long long basep =
            pack2(fmaf(wpx, Px, fmaf(wpy, Py, fmaf(wpz, Pz, bb1))), 0.0f);

        // phase 1: h1 for all 16 neighbors
        float* h1w = sH1[wid];
        const ulonglong2* rp = (const ulonglong2*)sR[wid];
        #pragma unroll
        for (int k = 0; k < 16; k++){
            ulonglong2 rv = rp[k];
            unsigned long long acc = fma2(w1a, rv.x, basep);
            acc = fma2(w1b, rv.y, acc);
            float lo, hi; unpack2(acc, lo, hi);
            h1w[k*32 + lane] = fmaxf(lo + hi, 0.0f);
        }
        __syncwarp();

        // phase 2: y_k = z_k + W3b @ h1_k ; max over k (b3 hoisted)
        float maxv = -3.4e38f;
        #pragma unroll
        for (int k = 0; k < 16; k++){
            const ulonglong2* hp2 = (const ulonglong2*)(h1w + k*32);
            unsigned long long c0 = pack2(zk[k], 0.0f), c1=0ull, c2=0ull, c3=0ull;
            #pragma unroll
            for (int c = 0; c < 8; c += 2){
                ulonglong2 v0 = hp2[c], v1 = hp2[c+1];
                c0 = fma2(w3bp[2*c+0], v0.x, c0);
                c1 = fma2(w3bp[2*c+1], v0.y, c1);
                c2 = fma2(w3bp[2*c+2], v1.x, c2);
                c3 = fma2(w3bp[2*c+3], v1.y, c3);
            }
            float l0,h0,l1,h1v,l2,h2,l3,h3;
            unpack2(c0,l0,h0); unpack2(c1,l1,h1v); unpack2(c2,l2,h2); unpack2(c3,l3,h3);
            float y = (l0+h0)+(l1+h1v)+(l2+h2)+(l3+h3);
            maxv = fmaxf(maxv, y);
        }
        maxv = fmaxf(maxv + bb3, 0.0f);   // relu commutes with max

        // build epilogue operand X[c][j]: c=lane -> maxv, c=lane+32 -> fself
        const float fself = g_f[(long)p*32 + lane];
        sX[lane*10 + wid]      = maxv;
        sX[(lane+32)*10 + wid] = fself;
        __syncthreads();

        // cooperative W4 GEMM: warp wid computes outputs [8*wid, 8*wid+8) x 8 points
        {
            const float* wcol = sW4T + wid*8 + olocal;
            const float* xrow = sX + 2*jp;
            unsigned long long acc = 0ull;
            #pragma unroll
            for (int c = 0; c < 64; c++){
                float wv = wcol[c*65];
                float2 xv = *(const float2*)(xrow + c*10);
                acc = fma2(pack2(wv, wv), pack2(xv.x, xv.y), acc);
            }
            float y0, y1; unpack2(acc, y0, y1);
            const float bb4 = sB4[wid*8 + olocal];
            y0 = fmaxf(y0 + bb4, 0.0f);
            y1 = fmaxf(y1 + bb4, 0.0f);
            const int p0 = grp*8;
            const int b0 = p0 / NN, nb = p0 - b0*NN;
            *(float2*)(out + ((long)b0*64 + wid*8 + olocal)*NN + nb + 2*jp)
                = make_float2(y0, y1);
        }
        __syncthreads();
    }
}

// ---------------------------------------------------------------------------
extern "C" void kernel_launch(void* const* d_in, const int* in_sizes, int n_in,
                              void* d_out, int out_size)
{
    const float *feature=0, *xyzp=0, *W1=0, *W2=0, *W3=0, *W4=0;
    const void* neigh=0;
    const float* s32[6] = {0,0,0,0,0,0};   // g1,b1,g2,b2,g3,b3 (encounter order)
    const float* s64[2] = {0,0};           // g4,b4
    int n2048 = 0, c32 = 0, c64 = 0;
    for (int i = 0; i < n_in; i++){
        int sz = in_sizes[i];
        const float* p = (const float*)d_in[i];
        if      (sz == 10485760) feature = p;
        else if (sz == 491520)   xyzp = p;
        else if (sz == 2621440)  neigh = d_in[i];
        else if (sz == 320)      W1 = p;
        else if (sz == 2048)     { if (n2048++ == 0) W2 = p; else W3 = p; }
        else if (sz == 4096)     W4 = p;
        else if (sz == 32)       { if (c32 < 6) s32[c32++] = p; }
        else if (sz == 64)       { if (c64 < 2) s64[c64++] = p; }
    }

    kernelA<<<1184, 256>>>(feature, W2, s32[2], s32[3], W3, s32[4], (const int*)neigh);
    kernelB<<<592, 256>>>(xyzp, (const int*)neigh,
                          W1, s32[0], s32[1],
                          W3, s32[4], s32[5],
                          W4, s64[0], s64[1],
                          (float*)d_out);
}

// round 10
// speedup vs baseline: 1.0169x; 1.0169x over previous
#include <cuda_runtime.h>

#define NN 40960
#define PT (4*NN)

__device__ float g_f[(long)PT*32];   // f = relu(s2*(W2@feat)+b2), [point][32]
__device__ float g_z[(long)PT*32];   // z = s3 * (W3a @ f), [point][32]
__device__ int g_is64;

__device__ __forceinline__ unsigned long long pack2(float lo, float hi){
    unsigned long long r;
    asm("mov.b64 %0, {%1, %2};" : "=l"(r) : "f"(lo), "f"(hi));
    return r;
}
__device__ __forceinline__ void unpack2(unsigned long long v, float& lo, float& hi){
    asm("mov.b64 {%0, %1}, %2;" : "=f"(lo), "=f"(hi) : "l"(v));
}
__device__ __forceinline__ unsigned long long fma2(unsigned long long a, unsigned long long b, unsigned long long c){
    unsigned long long d;
    asm("fma.rn.f32x2 %0, %1, %2, %3;" : "=l"(d) : "l"(a), "l"(b), "l"(c));
    return d;
}

// ---------------------------------------------------------------------------
// Kernel A: per point  f = relu(s2*(W2@x)+b2);  z = s3*(W3a@f)
__global__ void __launch_bounds__(256) kernelA(
    const float* __restrict__ feat,
    const float* __restrict__ W2, const float* __restrict__ g2, const float* __restrict__ b2,
    const float* __restrict__ W3, const float* __restrict__ g3,
    const int* __restrict__ neigh32)
{
    __shared__ __align__(16) float tile[64*68];      // [n][d] pitch 68 (16B rows)
    __shared__ __align__(16) float hs[8][2][32];     // double-buffered f

    const int tid  = threadIdx.x;
    const int lane = tid & 31;
    const int wid  = tid >> 5;

    if (blockIdx.x == 0 && tid == 0){
        int allzero = 1;
        #pragma unroll 1
        for (int i = 0; i < 128; i++)
            if (neigh32[2*i + 1] != 0) { allzero = 0; break; }
        g_is64 = allzero;
    }

    const float inv = rsqrtf(1.0f + 1e-5f);
    const float s2 = g2[lane]*inv, bb2 = b2[lane];
    const float s3 = g3[lane]*inv;

    unsigned long long w2p[32], w3ap[16];
    for (int i = tid; i < 2048; i += 256) tile[(i>>6)*66 + (i&63)] = W2[i];
    __syncthreads();
    #pragma unroll
    for (int c = 0; c < 32; c++)
        w2p[c] = pack2(tile[lane*66 + 2*c]*s2, tile[lane*66 + 2*c + 1]*s2);
    __syncthreads();
    for (int i = tid; i < 2048; i += 256) tile[(i>>6)*66 + (i&63)] = W3[i];
    __syncthreads();
    #pragma unroll
    for (int c = 0; c < 16; c++)
        w3ap[c] = pack2(tile[lane*66 + 2*c]*s3, tile[lane*66 + 2*c + 1]*s3);

    #pragma unroll 1
    for (int blk = blockIdx.x; blk < 2560; blk += gridDim.x){
        const int b  = blk / 640;
        const int n0 = (blk - b*640) * 64;
        const float* fb = feat + (long)b*64*NN;
        __syncthreads();
        for (int i = tid; i < 4096; i += 256){
            int d = i >> 6, n = i & 63;
            tile[n*68 + d] = fb[(long)d*NN + n0 + n];
        }
        __syncthreads();

        #pragma unroll 1
        for (int j = 0; j < 8; j++){
            const int n = wid*8 + j;
            const ulonglong2* xp2 = (const ulonglong2*)(tile + n*68);
            unsigned long long a0=0ull, a1=0ull, a2=0ull, a3=0ull;
            #pragma unroll
            for (int c = 0; c < 16; c += 2){
                ulonglong2 v0 = xp2[c], v1 = xp2[c+1];
                a0 = fma2(w2p[2*c+0], v0.x, a0);
                a1 = fma2(w2p[2*c+1], v0.y, a1);
                a2 = fma2(w2p[2*c+2], v1.x, a2);
                a3 = fma2(w2p[2*c+3], v1.y, a3);
            }
            float l0,h0,l1,h1,l2,h2,l3,h3;
            unpack2(a0,l0,h0); unpack2(a1,l1,h1); unpack2(a2,l2,h2); unpack2(a3,l3,h3);
            float f = fmaxf((l0+h0)+(l1+h1)+(l2+h2)+(l3+h3) + bb2, 0.0f);

            const long p = (long)b*NN + n0 + n;
            float* hb = hs[wid][j & 1];
            hb[lane] = f;
            g_f[p*32 + lane] = f;
            __syncwarp();

            const ulonglong2* hp2 = (const ulonglong2*)hb;
            unsigned long long z0=0ull, z1=0ull, z2=0ull, z3=0ull;
            #pragma unroll
            for (int c = 0; c < 8; c += 2){
                ulonglong2 v0 = hp2[c], v1 = hp2[c+1];
                z0 = fma2(w3ap[2*c+0], v0.x, z0);
                z1 = fma2(w3ap[2*c+1], v0.y, z1);
                z2 = fma2(w3ap[2*c+2], v1.x, z2);
                z3 = fma2(w3ap[2*c+3], v1.y, z3);
            }
            unpack2(z0,l0,h0); unpack2(z1,l1,h1); unpack2(z2,l2,h2); unpack2(z3,l3,h3);
            g_z[p*32 + lane] = (l0+h0)+(l1+h1)+(l2+h2)+(l3+h3);
        }
    }
}

// ---------------------------------------------------------------------------
// Kernel B: persistent, one warp per point; block-cooperative W4 epilogue
// (4-way split accumulators, double-buffered operand -> 1 barrier/group).
__global__ void __launch_bounds__(256, 2) kernelB(
    const float* __restrict__ xyz, const int* __restrict__ neigh32,
    const float* __restrict__ W1, const float* __restrict__ g1, const float* __restrict__ b1,
    const float* __restrict__ W3, const float* __restrict__ g3, const float* __restrict__ b3,
    const float* __restrict__ W4, const float* __restrict__ g4, const float* __restrict__ b4,
    float* __restrict__ out)
{
    __shared__ __align__(16) float sW4T[64*65];      // [c][o] pitch 65, scale folded
    __shared__ float sB4[64];
    __shared__ __align__(16) float sR[8][16*4];      // per-warp (dist,rx,ry,rz)x16
    __shared__ __align__(16) float sH1[8][16*32];    // per-warp h1[k][h]
    __shared__ __align__(16) float sX[2][64*10];     // double-buffered [c][j] pitch 10

    const int tid  = threadIdx.x;
    const int lane = tid & 31;
    const int wid  = tid >> 5;
    const float inv = rsqrtf(1.0f + 1e-5f);

    // W1 folded: u=[dist,r,P,Q], Q=P-r => W1@u = wd*dist + (Wr-WQ)@r + (WP+WQ)@P
    const float s1 = g1[lane]*inv, bb1 = b1[lane];
    const float s3 = g3[lane]*inv, bb3 = b3[lane];
    float wd   = W1[lane*10 + 0]*s1;
    float wrx  = (W1[lane*10 + 1] - W1[lane*10 + 7])*s1;
    float wry  = (W1[lane*10 + 2] - W1[lane*10 + 8])*s1;
    float wrz  = (W1[lane*10 + 3] - W1[lane*10 + 9])*s1;
    float wpx  = (W1[lane*10 + 4] + W1[lane*10 + 7])*s1;
    float wpy  = (W1[lane*10 + 5] + W1[lane*10 + 8])*s1;
    float wpz  = (W1[lane*10 + 6] + W1[lane*10 + 9])*s1;
    const unsigned long long w1a = pack2(wd,  wrx);   // * (dist, rx)
    const unsigned long long w1b = pack2(wry, wrz);   // * (ry, rz)

    // stage W3 coalesced into sH1, read rows (pitch 66)
    unsigned long long w3bp[16];
    {
        float* wt = (float*)sH1;
        for (int i = tid; i < 2048; i += 256) wt[(i>>6)*66 + (i&63)] = W3[i];
        __syncthreads();
        #pragma unroll
        for (int c = 0; c < 16; c++)
            w3bp[c] = pack2(wt[lane*66 + 32 + 2*c]*s3, wt[lane*66 + 33 + 2*c]*s3);
        __syncthreads();
    }
    // W4 transposed + scale folded: sW4T[c*65 + o] = W4[o][c]*s4[o]
    for (int i = tid; i < 4096; i += 256){
        int o = i >> 6, c = i & 63;
        sW4T[c*65 + o] = W4[o*64 + c] * (g4[o]*inv);
    }
    if (tid < 64) sB4[tid] = b4[tid];

    const int is64 = g_is64;
    __syncthreads();

    const int olocal = lane >> 2;          // epilogue: output o = wid*8 + olocal
    const int jp     = lane & 3;           // epilogue: points j = 2jp, 2jp+1
    int buf = 0;

    #pragma unroll 1
    for (int grp = blockIdx.x; grp < PT/8; grp += gridDim.x){
        const int p = grp*8 + wid;
        const int b = p / NN, n = p - b*NN;
        const float* xb = xyz + (long)b*NN*3;
        const float* zb = g_z + (long)b*NN*32;
        const float Px = xb[n*3+0], Py = xb[n*3+1], Pz = xb[n*3+2];

        // phase 0: lanes<16 compute their neighbor's geometry in parallel
        int myidx = 0;
        if (lane < 16){
            myidx = is64 ? neigh32[2*(p*16 + lane)] : neigh32[p*16 + lane];
            float Qx = xb[myidx*3+0], Qy = xb[myidx*3+1], Qz = xb[myidx*3+2];
            float rx = Px - Qx, ry = Py - Qy, rz = Pz - Qz;
            float dist = sqrtf(rx*rx + ry*ry + rz*rz);
            ((float4*)sR[wid])[lane] = make_float4(dist, rx, ry, rz);
        }

        // batched z gathers (MLP=16)
        float zk[16];
        #pragma unroll
        for (int k = 0; k < 16; k++){
            int id = __shfl_sync(0xffffffffu, myidx, k);
            zk[k] = zb[id*32 + lane];
        }
        __syncwarp();

        const unsigned long long basep =
            pack2(fmaf(wpx, Px, fmaf(wpy, Py, fmaf(wpz, Pz, bb1))), 0.0f);

        // phase 1: h1 for all 16 neighbors
        float* h1w = sH1[wid];
        const ulonglong2* rp = (const ulonglong2*)sR[wid];
        #pragma unroll
        for (int k = 0; k < 16; k++){
            ulonglong2 rv = rp[k];
            unsigned long long acc = fma2(w1a, rv.x, basep);
            acc = fma2(w1b, rv.y, acc);
            float lo, hi; unpack2(acc, lo, hi);
            h1w[k*32 + lane] = fmaxf(lo + hi, 0.0f);
        }
        __syncwarp();

        // phase 2: y_k = z_k + W3b @ h1_k ; max over k (b3 hoisted)
        float maxv = -3.4e38f;
        #pragma unroll
        for (int k = 0; k < 16; k++){
            const ulonglong2* hp2 = (const ulonglong2*)(h1w + k*32);
            unsigned long long c0 = pack2(zk[k], 0.0f), c1=0ull, c2=0ull, c3=0ull;
            #pragma unroll
            for (int c = 0; c < 8; c += 2){
                ulonglong2 v0 = hp2[c], v1 = hp2[c+1];
                c0 = fma2(w3bp[2*c+0], v0.x, c0);
                c1 = fma2(w3bp[2*c+1], v0.y, c1);
                c2 = fma2(w3bp[2*c+2], v1.x, c2);
                c3 = fma2(w3bp[2*c+3], v1.y, c3);
            }
            float l0,h0,l1,h1v,l2,h2,l3,h3;
            unpack2(c0,l0,h0); unpack2(c1,l1,h1v); unpack2(c2,l2,h2); unpack2(c3,l3,h3);
            float y = (l0+h0)+(l1+h1v)+(l2+h2)+(l3+h3);
            maxv = fmaxf(maxv, y);
        }
        maxv = fmaxf(maxv + bb3, 0.0f);   // relu commutes with max

        // build epilogue operand X[c][j]: c=lane -> maxv, c=lane+32 -> fself
        const float fself = g_f[(long)p*32 + lane];
        float* sXb = sX[buf];
        sXb[lane*10 + wid]      = maxv;
        sXb[(lane+32)*10 + wid] = fself;
        __syncthreads();

        // cooperative W4 GEMM: warp wid computes outputs [8*wid, 8*wid+8) x 8 points
        {
            const float* wcol = sW4T + wid*8 + olocal;
            const float* xrow = sXb + 2*jp;
            unsigned long long a0=0ull, a1=0ull, a2=0ull, a3=0ull;
            #pragma unroll
            for (int c = 0; c < 64; c += 4){
                float w0 = wcol[(c+0)*65];
                float w1 = wcol[(c+1)*65];
                float w2 = wcol[(c+2)*65];
                float w3 = wcol[(c+3)*65];
                float2 x0 = *(const float2*)(xrow + (c+0)*10);
                float2 x1 = *(const float2*)(xrow + (c+1)*10);
                float2 x2 = *(const float2*)(xrow + (c+2)*10);
                float2 x3 = *(const float2*)(xrow + (c+3)*10);
                a0 = fma2(pack2(w0, w0), pack2(x0.x, x0.y), a0);
                a1 = fma2(pack2(w1, w1), pack2(x1.x, x1.y), a1);
                a2 = fma2(pack2(w2, w2), pack2(x2.x, x2.y), a2);
                a3 = fma2(pack2(w3, w3), pack2(x3.x, x3.y), a3);
            }
            float p0a, p0b, p1a, p1b, p2a, p2b, p3a, p3b;
            unpack2(a0, p0a, p0b); unpack2(a1, p1a, p1b);
            unpack2(a2, p2a, p2b); unpack2(a3, p3a, p3b);
            float y0 = (p0a + p1a) + (p2a + p3a);
            float y1 = (p0b + p1b) + (p2b + p3b);
            const float bb4 = sB4[wid*8 + olocal];
            y0 = fmaxf(y0 + bb4, 0.0f);
            y1 = fmaxf(y1 + bb4, 0.0f);
            const int pg = grp*8;
            const int b0 = pg / NN, nb = pg - b0*NN;
            *(float2*)(out + ((long)b0*64 + wid*8 + olocal)*NN + nb + 2*jp)
                = make_float2(y0, y1);
        }
        buf ^= 1;   // no trailing barrier needed: next group writes the other buffer
    }
}

// ---------------------------------------------------------------------------
extern "C" void kernel_launch(void* const* d_in, const int* in_sizes, int n_in,
                              void* d_out, int out_size)
{
    const float *feature=0, *xyzp=0, *W1=0, *W2=0, *W3=0, *W4=0;
    const void* neigh=0;
    const float* s32[6] = {0,0,0,0,0,0};   // g1,b1,g2,b2,g3,b3 (encounter order)
    const float* s64[2] = {0,0};           // g4,b4
    int n2048 = 0, c32 = 0, c64 = 0;
    for (int i = 0; i < n_in; i++){
        int sz = in_sizes[i];
        const float* p = (const float*)d_in[i];
        if      (sz == 10485760) feature = p;
        else if (sz == 491520)   xyzp = p;
        else if (sz == 2621440)  neigh = d_in[i];
        else if (sz == 320)      W1 = p;
        else if (sz == 2048)     { if (n2048++ == 0) W2 = p; else W3 = p; }
        else if (sz == 4096)     W4 = p;
        else if (sz == 32)       { if (c32 < 6) s32[c32++] = p; }
        else if (sz == 64)       { if (c64 < 2) s64[c64++] = p; }
    }

    kernelA<<<1184, 256>>>(feature, W2, s32[2], s32[3], W3, s32[4], (const int*)neigh);
    kernelB<<<592, 256>>>(xyzp, (const int*)neigh,
                          W1, s32[0], s32[1],
                          W3, s32[4], s32[5],
                          W4, s64[0], s64[1],
                          (float*)d_out);
}

// round 11
// speedup vs baseline: 1.1346x; 1.1158x over previous
#include <cuda_runtime.h>

#define NN 40960
#define PT (4*NN)

__device__ float g_f[(long)PT*32];   // f = relu(s2*(W2@feat)+b2), [point][32]
__device__ float g_z[(long)PT*32];   // z = s3 * (W3a @ f), [point][32]
__device__ int g_is64;

__device__ __forceinline__ unsigned long long pack2(float lo, float hi){
    unsigned long long r;
    asm("mov.b64 %0, {%1, %2};" : "=l"(r) : "f"(lo), "f"(hi));
    return r;
}
__device__ __forceinline__ void unpack2(unsigned long long v, float& lo, float& hi){
    asm("mov.b64 {%0, %1}, %2;" : "=f"(lo), "=f"(hi) : "l"(v));
}
__device__ __forceinline__ unsigned long long fma2(unsigned long long a, unsigned long long b, unsigned long long c){
    unsigned long long d;
    asm("fma.rn.f32x2 %0, %1, %2, %3;" : "=l"(d) : "l"(a), "l"(b), "l"(c));
    return d;
}

// ---------------------------------------------------------------------------
// Kernel A: per point  f = relu(s2*(W2@x)+b2);  z = s3*(W3a@f)
__global__ void __launch_bounds__(256) kernelA(
    const float* __restrict__ feat,
    const float* __restrict__ W2, const float* __restrict__ g2, const float* __restrict__ b2,
    const float* __restrict__ W3, const float* __restrict__ g3,
    const int* __restrict__ neigh32)
{
    __shared__ __align__(16) float tile[64*68];      // [n][d] pitch 68 (16B rows)
    __shared__ __align__(16) float hs[8][2][32];     // double-buffered f

    const int tid  = threadIdx.x;
    const int lane = tid & 31;
    const int wid  = tid >> 5;

    if (blockIdx.x == 0 && tid == 0){
        int allzero = 1;
        #pragma unroll 1
        for (int i = 0; i < 128; i++)
            if (neigh32[2*i + 1] != 0) { allzero = 0; break; }
        g_is64 = allzero;
    }

    const float inv = rsqrtf(1.0f + 1e-5f);
    const float s2 = g2[lane]*inv, bb2 = b2[lane];
    const float s3 = g3[lane]*inv;

    unsigned long long w2p[32], w3ap[16];
    for (int i = tid; i < 2048; i += 256) tile[(i>>6)*66 + (i&63)] = W2[i];
    __syncthreads();
    #pragma unroll
    for (int c = 0; c < 32; c++)
        w2p[c] = pack2(tile[lane*66 + 2*c]*s2, tile[lane*66 + 2*c + 1]*s2);
    __syncthreads();
    for (int i = tid; i < 2048; i += 256) tile[(i>>6)*66 + (i&63)] = W3[i];
    __syncthreads();
    #pragma unroll
    for (int c = 0; c < 16; c++)
        w3ap[c] = pack2(tile[lane*66 + 2*c]*s3, tile[lane*66 + 2*c + 1]*s3);

    #pragma unroll 1
    for (int blk = blockIdx.x; blk < 2560; blk += gridDim.x){
        const int b  = blk / 640;
        const int n0 = (blk - b*640) * 64;
        const float* fb = feat + (long)b*64*NN;
        __syncthreads();
        for (int i = tid; i < 4096; i += 256){
            int d = i >> 6, n = i & 63;
            tile[n*68 + d] = fb[(long)d*NN + n0 + n];
        }
        __syncthreads();

        #pragma unroll 1
        for (int j = 0; j < 8; j++){
            const int n = wid*8 + j;
            const ulonglong2* xp2 = (const ulonglong2*)(tile + n*68);
            unsigned long long a0=0ull, a1=0ull, a2=0ull, a3=0ull;
            #pragma unroll
            for (int c = 0; c < 16; c += 2){
                ulonglong2 v0 = xp2[c], v1 = xp2[c+1];
                a0 = fma2(w2p[2*c+0], v0.x, a0);
                a1 = fma2(w2p[2*c+1], v0.y, a1);
                a2 = fma2(w2p[2*c+2], v1.x, a2);
                a3 = fma2(w2p[2*c+3], v1.y, a3);
            }
            float l0,h0,l1,h1,l2,h2,l3,h3;
            unpack2(a0,l0,h0); unpack2(a1,l1,h1); unpack2(a2,l2,h2); unpack2(a3,l3,h3);
            float f = fmaxf((l0+h0)+(l1+h1)+(l2+h2)+(l3+h3) + bb2, 0.0f);

            const long p = (long)b*NN + n0 + n;
            float* hb = hs[wid][j & 1];
            hb[lane] = f;
            g_f[p*32 + lane] = f;
            __syncwarp();

            const ulonglong2* hp2 = (const ulonglong2*)hb;
            unsigned long long z0=0ull, z1=0ull, z2=0ull, z3=0ull;
            #pragma unroll
            for (int c = 0; c < 8; c += 2){
                ulonglong2 v0 = hp2[c], v1 = hp2[c+1];
                z0 = fma2(w3ap[2*c+0], v0.x, z0);
                z1 = fma2(w3ap[2*c+1], v0.y, z1);
                z2 = fma2(w3ap[2*c+2], v1.x, z2);
                z3 = fma2(w3ap[2*c+3], v1.y, z3);
            }
            unpack2(z0,l0,h0); unpack2(z1,l1,h1); unpack2(z2,l2,h2); unpack2(z3,l3,h3);
            g_z[p*32 + lane] = (l0+h0)+(l1+h1)+(l2+h2)+(l3+h3);
        }
    }
}

// ---------------------------------------------------------------------------
// Kernel B: persistent, one warp per point (R8 structure), forced 3 blocks/SM.
__global__ void __launch_bounds__(256, 3) kernelB(
    const float* __restrict__ xyz, const int* __restrict__ neigh32,
    const float* __restrict__ W1, const float* __restrict__ g1, const float* __restrict__ b1,
    const float* __restrict__ W3, const float* __restrict__ g3, const float* __restrict__ b3,
    const float* __restrict__ W4, const float* __restrict__ g4, const float* __restrict__ b4,
    float* __restrict__ out)
{
    __shared__ __align__(16) unsigned long long sW4[32*64];  // [c_pair][o]
    __shared__ float sB4[64];
    __shared__ __align__(16) float sR[8][16*4];              // per-warp (dist,rx,ry,rz)x16
    __shared__ __align__(16) float sH1[8][16*32];            // per-warp h1[k][h]
    __shared__ __align__(16) float sE[8][64];
    __shared__ float sOut[64][9];

    const int tid  = threadIdx.x;
    const int lane = tid & 31;
    const int wid  = tid >> 5;
    const float inv = rsqrtf(1.0f + 1e-5f);

    // W1 folded: u=[dist,r,P,Q], Q=P-r => W1@u = wd*dist + (Wr-WQ)@r + (WP+WQ)@P
    const float s1 = g1[lane]*inv, bb1 = b1[lane];
    const float s3 = g3[lane]*inv, bb3 = b3[lane];
    float wd   = W1[lane*10 + 0]*s1;
    float wrx  = (W1[lane*10 + 1] - W1[lane*10 + 7])*s1;
    float wry  = (W1[lane*10 + 2] - W1[lane*10 + 8])*s1;
    float wrz  = (W1[lane*10 + 3] - W1[lane*10 + 9])*s1;
    float wpx  = (W1[lane*10 + 4] + W1[lane*10 + 7])*s1;
    float wpy  = (W1[lane*10 + 5] + W1[lane*10 + 8])*s1;
    float wpz  = (W1[lane*10 + 6] + W1[lane*10 + 9])*s1;
    const unsigned long long w1a = pack2(wd,  wrx);   // * (dist, rx)
    const unsigned long long w1b = pack2(wry, wrz);   // * (ry, rz)

    // stage W3 coalesced into sH1, read rows (pitch 66)
    unsigned long long w3bp[16];
    {
        float* wt = (float*)sH1;
        for (int i = tid; i < 2048; i += 256) wt[(i>>6)*66 + (i&63)] = W3[i];
        __syncthreads();
        #pragma unroll
        for (int c = 0; c < 16; c++)
            w3bp[c] = pack2(wt[lane*66 + 32 + 2*c]*s3, wt[lane*66 + 33 + 2*c]*s3);
        __syncthreads();
    }
    for (int i = tid; i < 2048; i += 256){
        int c2 = i >> 6, o = i & 63;
        float2 wv = ((const float2*)W4)[o*32 + c2];
        float s4 = g4[o] * inv;
        sW4[i] = pack2(wv.x*s4, wv.y*s4);
    }
    if (tid < 64) sB4[tid] = b4[tid];

    const int is64 = g_is64;
    __syncthreads();

    #pragma unroll 1
    for (int grp = blockIdx.x; grp < PT/8; grp += gridDim.x){
        const int p = grp*8 + wid;
        const int b = p / NN, n = p - b*NN;
        const float* xb = xyz + (long)b*NN*3;
        const float* zb = g_z + (long)b*NN*32;
        const float Px = xb[n*3+0], Py = xb[n*3+1], Pz = xb[n*3+2];

        // phase 0: lanes<16 compute their neighbor's geometry in parallel
        int myidx = 0;
        if (lane < 16){
            myidx = is64 ? neigh32[2*(p*16 + lane)] : neigh32[p*16 + lane];
            float Qx = xb[myidx*3+0], Qy = xb[myidx*3+1], Qz = xb[myidx*3+2];
            float rx = Px - Qx, ry = Py - Qy, rz = Pz - Qz;
            float dist = sqrtf(rx*rx + ry*ry + rz*rz);
            ((float4*)sR[wid])[lane] = make_float4(dist, rx, ry, rz);
        }

        // batched z gathers (MLP=16)
        float zk[16];
        #pragma unroll
        for (int k = 0; k < 16; k++){
            int id = __shfl_sync(0xffffffffu, myidx, k);
            zk[k] = zb[id*32 + lane];
        }
        __syncwarp();

        const unsigned long long basep =
            pack2(fmaf(wpx, Px, fmaf(wpy, Py, fmaf(wpz, Pz, bb1))), 0.0f);

        // phase 1: h1 for all 16 neighbors
        float* h1w = sH1[wid];
        const ulonglong2* rp = (const ulonglong2*)sR[wid];
        #pragma unroll
        for (int k = 0; k < 16; k++){
            ulonglong2 rv = rp[k];
            unsigned long long acc = fma2(w1a, rv.x, basep);
            acc = fma2(w1b, rv.y, acc);
            float lo, hi; unpack2(acc, lo, hi);
            h1w[k*32 + lane] = fmaxf(lo + hi, 0.0f);
        }
        __syncwarp();

        // phase 2: y_k = z_k + W3b @ h1_k ; max over k (b3 hoisted)
        float maxv = -3.4e38f;
        #pragma unroll
        for (int k = 0; k < 16; k++){
            const ulonglong2* hp2 = (const ulonglong2*)(h1w + k*32);
            unsigned long long c0 = pack2(zk[k], 0.0f), c1=0ull, c2=0ull, c3=0ull;
            #pragma unroll
            for (int c = 0; c < 8; c += 2){
                ulonglong2 v0 = hp2[c], v1 = hp2[c+1];
                c0 = fma2(w3bp[2*c+0], v0.x, c0);
                c1 = fma2(w3bp[2*c+1], v0.y, c1);
                c2 = fma2(w3bp[2*c+2], v1.x, c2);
                c3 = fma2(w3bp[2*c+3], v1.y, c3);
            }
            float l0,h0,l1,h1v,l2,h2,l3,h3;
            unpack2(c0,l0,h0); unpack2(c1,l1,h1v); unpack2(c2,l2,h2); unpack2(c3,l3,h3);
            float y = (l0+h0)+(l1+h1v)+(l2+h2)+(l3+h3);
            maxv = fmaxf(maxv, y);
        }
        maxv = fmaxf(maxv + bb3, 0.0f);   // relu commutes with max

        const float fself = g_f[(long)p*32 + lane];
        sE[wid][lane]      = maxv;
        sE[wid][32 + lane] = fself;
        __syncwarp();
        const ulonglong2* ep2 = (const ulonglong2*)sE[wid];
        unsigned long long e0a=0ull, e0b=0ull, e1a=0ull, e1b=0ull;
        #pragma unroll
        for (int c = 0; c < 32; c += 2){
            ulonglong2 v = ep2[c >> 1];
            e0a = fma2(sW4[(c+0)*64 + lane],      v.x, e0a);
            e0b = fma2(sW4[(c+1)*64 + lane],      v.y, e0b);
            e1a = fma2(sW4[(c+0)*64 + lane + 32], v.x, e1a);
            e1b = fma2(sW4[(c+1)*64 + lane + 32], v.y, e1b);
        }
        float l0,h0,l1,h1v,l2,h2,l3,h3;
        unpack2(e0a,l0,h0); unpack2(e0b,l1,h1v); unpack2(e1a,l2,h2); unpack2(e1b,l3,h3);
        float o0 = fmaxf(sB4[lane]      + (l0+h0)+(l1+h1v), 0.0f);
        float o1 = fmaxf(sB4[lane + 32] + (l2+h2)+(l3+h3),  0.0f);
        __syncwarp();

        sOut[lane][wid]      = o0;
        sOut[lane + 32][wid] = o1;
        __syncthreads();
        for (int i = tid; i < 512; i += 256){
            int o = i >> 3, j = i & 7;
            int pp = grp*8 + j;
            int b2_ = pp / NN, n2_ = pp - b2_*NN;
            out[((long)b2_*64 + o)*NN + n2_] = sOut[o][j];
        }
        __syncthreads();
    }
}

// ---------------------------------------------------------------------------
extern "C" void kernel_launch(void* const* d_in, const int* in_sizes, int n_in,
                              void* d_out, int out_size)
{
    const float *feature=0, *xyzp=0, *W1=0, *W2=0, *W3=0, *W4=0;
    const void* neigh=0;
    const float* s32[6] = {0,0,0,0,0,0};   // g1,b1,g2,b2,g3,b3 (encounter order)
    const float* s64[2] = {0,0};           // g4,b4
    int n2048 = 0, c32 = 0, c64 = 0;
    for (int i = 0; i < n_in; i++){
        int sz = in_sizes[i];
        const float* p = (const float*)d_in[i];
        if      (sz == 10485760) feature = p;
        else if (sz == 491520)   xyzp = p;
        else if (sz == 2621440)  neigh = d_in[i];
        else if (sz == 320)      W1 = p;
        else if (sz == 2048)     { if (n2048++ == 0) W2 = p; else W3 = p; }
        else if (sz == 4096)     W4 = p;
        else if (sz == 32)       { if (c32 < 6) s32[c32++] = p; }
        else if (sz == 64)       { if (c64 < 2) s64[c64++] = p; }
    }

    kernelA<<<1184, 256>>>(feature, W2, s32[2], s32[3], W3, s32[4], (const int*)neigh);
    kernelB<<<444, 256>>>(xyzp, (const int*)neigh,
                          W1, s32[0], s32[1],
                          W3, s32[4], s32[5],
                          W4, s64[0], s64[1],
                          (float*)d_out);
}